// round 1
// baseline (speedup 1.0000x reference)
#include <cuda_runtime.h>

#define D   256
#define H   4
#define DK  64

#define MAP_CAP   65536
#define COMP_CAP  16384
#define MAXE      256
#define BMAX      256

// ---------------- device scratch (no allocations allowed) ----------------
__device__ int   g_is64;
__device__ int   g_count;
__device__ int   g_map[MAP_CAP];
__device__ int   g_csrc[COMP_CAP];
__device__ int   g_cb[COMP_CAP];
__device__ int   g_ce[COMP_CAP];
__device__ float g_qwk[BMAX * H * D];

__device__ __forceinline__ long long idx_at(const void* p, long long i, int is64) {
    if (is64) return ((const long long*)p)[i];
    return (long long)((const int*)p)[i];
}

// ---------------- kernel 1: probe index dtype, reset counter -------------
__global__ void probe_kernel(const int* src32, int ne) {
    if (threadIdx.x == 0 && blockIdx.x == 0) {
        // If data is int64 (values < 2^31, nonneg), every odd 32-bit word is 0.
        int n = ne < 256 ? ne : 256;
        int all0 = 1;
        for (int i = 0; i < n; i++) {
            if (src32[2 * i + 1] != 0) { all0 = 0; break; }
        }
        g_is64 = all0;
        g_count = 0;
    }
}

// ---------------- kernel 2: init node->batch map -------------------------
__global__ void init_map_kernel(int nv) {
    int i = blockIdx.x * blockDim.x + threadIdx.x;
    int lim = nv < MAP_CAP ? nv : MAP_CAP;
    if (i < lim) g_map[i] = -1;
}

// ---------------- kernel 3: scatter glob_idx into map --------------------
__global__ void scatter_map_kernel(const void* glob_idx, int b) {
    int i = blockIdx.x * blockDim.x + threadIdx.x;
    if (i < b) {
        long long node = idx_at(glob_idx, i, g_is64);
        if (node >= 0 && node < MAP_CAP) g_map[node] = i;
    }
}

// ---------------- kernel 4: qWK[b][h][c] = scale * (q_b @ WQ^T)_hd WK_hd,c
// one block per batch row, 256 threads
__global__ void qwk_kernel(const float* __restrict__ query,
                           const float* __restrict__ WQ,
                           const float* __restrict__ WK) {
    __shared__ float qb[D];
    int b = blockIdx.x, t = threadIdx.x;

    // qb[t] = sum_k query[b][k] * WQ[t][k]
    const float* qr = query + (size_t)b * D;
    const float* wr = WQ + (size_t)t * D;
    float acc = 0.f;
#pragma unroll 8
    for (int k = 0; k < D; k++) acc += qr[k] * wr[k];
    qb[t] = acc;
    __syncthreads();

    // qwk[b][h][t] = 0.125 * sum_d qb[h*64+d] * WK[h*64+d][t]
#pragma unroll
    for (int h = 0; h < H; h++) {
        float a = 0.f;
#pragma unroll 8
        for (int d = 0; d < DK; d++)
            a += qb[h * DK + d] * WK[(size_t)(h * DK + d) * D + t];
        g_qwk[((size_t)b * H + h) * D + t] = a * 0.125f;  // 1/sqrt(64)
    }
}

// ---------------- kernel 5: filter + compact relevant edges --------------
__global__ void filter_kernel(const void* __restrict__ src,
                              const void* __restrict__ dst, int ne) {
    int is64 = g_is64;
    int stride = gridDim.x * blockDim.x;
    for (int i = blockIdx.x * blockDim.x + threadIdx.x; i < ne; i += stride) {
        long long d = idx_at(dst, i, is64);
        if (d >= 0 && d < MAP_CAP) {
            int b = g_map[d];
            if (b >= 0) {
                int pos = atomicAdd(&g_count, 1);
                if (pos < COMP_CAP) {
                    g_csrc[pos] = (int)idx_at(src, i, is64);
                    g_cb[pos]   = b;
                    g_ce[pos]   = i;
                }
            }
        }
    }
}

// ---------------- kernel 6: per-batch-row attention + WV + WO ------------
// one block per batch row b, 256 threads
__global__ void attn_kernel(const float* __restrict__ x,
                            const float* __restrict__ WV,
                            const float* __restrict__ WO,
                            float* __restrict__ out) {
    int b = blockIdx.x, t = threadIdx.x;

    __shared__ int   s_src[MAXE];
    __shared__ int   s_eid[MAXE];
    __shared__ float s_s[MAXE][H];     // scores -> alphas
    __shared__ float s_buf[H][D];      // qwk, later xacc
    __shared__ float s_row[D];
    __shared__ int   s_cnt, s_me;

    if (t == 0) s_cnt = 0;
#pragma unroll
    for (int h = 0; h < H; h++)
        s_buf[h][t] = g_qwk[((size_t)b * H + h) * D + t];
    __syncthreads();

    // gather this row's edges (parallel, then sort by edge id => deterministic)
    int cnt = g_count;
    if (cnt > COMP_CAP) cnt = COMP_CAP;
    for (int p = t; p < cnt; p += blockDim.x) {
        if (g_cb[p] == b) {
            int q = atomicAdd(&s_cnt, 1);
            if (q < MAXE) { s_src[q] = g_csrc[p]; s_eid[q] = g_ce[p]; }
        }
    }
    __syncthreads();
    if (t == 0) {
        int me = s_cnt < MAXE ? s_cnt : MAXE;
        for (int i = 1; i < me; i++) {   // insertion sort by original edge id
            int e = s_eid[i], sv = s_src[i];
            int j = i - 1;
            while (j >= 0 && s_eid[j] > e) {
                s_eid[j + 1] = s_eid[j]; s_src[j + 1] = s_src[j]; j--;
            }
            s_eid[j + 1] = e; s_src[j + 1] = sv;
        }
        s_me = me;
    }
    __syncthreads();
    int me = s_me;

    // scores: warp per (edge, head) pair
    int warp = t >> 5, lane = t & 31;
    for (int p = warp; p < me * H; p += 8) {
        int i = p >> 2, h = p & 3;
        const float* xr = x + (size_t)s_src[i] * D;
        float a = 0.f;
        for (int c = lane; c < D; c += 32) a += xr[c] * s_buf[h][c];
#pragma unroll
        for (int o = 16; o; o >>= 1) a += __shfl_down_sync(0xffffffffu, a, o);
        if (lane == 0) s_s[i][h] = a;
    }
    __syncthreads();

    // softmax per head (tiny, serial per head)
    if (t < H) {
        float m = -1e30f;
        for (int i = 0; i < me; i++) m = fmaxf(m, s_s[i][t]);
        float sum = 0.f;
        for (int i = 0; i < me; i++) {
            float e = expf(s_s[i][t] - m);
            s_s[i][t] = e; sum += e;
        }
        float inv = sum > 0.f ? 1.f / sum : 0.f;
        for (int i = 0; i < me; i++) s_s[i][t] *= inv;
    }
    __syncthreads();

    // aggregate: xacc[h][c] = sum_i alpha[i][h] * x[src_i][c]   (c = t)
    float a0 = 0.f, a1 = 0.f, a2 = 0.f, a3 = 0.f;
    for (int i = 0; i < me; i++) {
        float xv = x[(size_t)s_src[i] * D + t];
        a0 += s_s[i][0] * xv; a1 += s_s[i][1] * xv;
        a2 += s_s[i][2] * xv; a3 += s_s[i][3] * xv;
    }
    __syncthreads();               // done reading s_buf as qwk
    s_buf[0][t] = a0; s_buf[1][t] = a1; s_buf[2][t] = a2; s_buf[3][t] = a3;
    __syncthreads();

    // V projection: row[j] = sum_c xacc[h(j)][c] * WV[j][c]   (j = t)
    {
        int h = t / DK;
        const float* wr = WV + (size_t)t * D;
        float a = 0.f;
#pragma unroll 8
        for (int c = 0; c < D; c++) a += s_buf[h][c] * wr[c];
        s_row[t] = a;
    }
    __syncthreads();

    // O projection: out[b][j] = sum_k row[k] * WO[j][k]
    {
        const float* wr = WO + (size_t)t * D;
        float a = 0.f;
#pragma unroll 8
        for (int k = 0; k < D; k++) a += s_row[k] * wr[k];
        out[(size_t)b * D + t] = a;
    }
}

// ---------------- launch ------------------------------------------------
extern "C" void kernel_launch(void* const* d_in, const int* in_sizes, int n_in,
                              void* d_out, int out_size) {
    const float* query = (const float*)d_in[0];
    const float* x     = (const float*)d_in[1];
    const float* WQ    = (const float*)d_in[2];
    const float* WK    = (const float*)d_in[3];
    const float* WV    = (const float*)d_in[4];
    const float* WO    = (const float*)d_in[5];
    const void*  src   = d_in[6];
    const void*  dst   = d_in[7];
    const void*  gidx  = d_in[8];

    int B  = in_sizes[0] / D;
    int NV = in_sizes[1] / D;
    int NE = in_sizes[6];
    float* out = (float*)d_out;

    probe_kernel<<<1, 32>>>((const int*)src, NE);
    init_map_kernel<<<(NV + 255) / 256, 256>>>(NV);
    scatter_map_kernel<<<(B + 63) / 64, 64>>>(gidx, B);
    qwk_kernel<<<B, 256>>>(query, WQ, WK);
    filter_kernel<<<(NE + 255) / 256, 256>>>(src, dst, NE);
    attn_kernel<<<B, 256>>>(x, WV, WO, out);
}

// round 4
// speedup vs baseline: 3.4130x; 3.4130x over previous
#include <cuda_runtime.h>

#define D   256
#define H   4
#define DK  64

#define MAP_CAP   65536
#define COMP_CAP  16384
#define MAXE      256
#define BMAX      256

// ---------------- device scratch (no allocations allowed) ----------------
__device__ int   g_is64;
__device__ int   g_count;
__device__ int   g_map[MAP_CAP];
__device__ int   g_csrc[COMP_CAP];
__device__ int   g_cb[COMP_CAP];
__device__ int   g_ce[COMP_CAP];
__device__ float g_qb[BMAX * D];
__device__ float g_qwk[BMAX * H * D];

__device__ __forceinline__ long long idx_at(const void* p, long long i, int is64) {
    if (is64) return ((const long long*)p)[i];
    return (long long)((const int*)p)[i];
}

__device__ __forceinline__ float warp_sum(float a) {
#pragma unroll
    for (int o = 16; o; o >>= 1) a += __shfl_down_sync(0xffffffffu, a, o);
    return a;
}

// dot of a 256-float global row with a 256-float shared row, one warp,
// float4-vectorized: lane reads 16B chunks at lane*4 and lane*4+128.
__device__ __forceinline__ float warp_dot256(const float* __restrict__ g,
                                             const float* __restrict__ s,
                                             int lane) {
    const float4* g4 = (const float4*)g;
    const float4* s4 = (const float4*)s;
    float4 ga = g4[lane],        sa = s4[lane];
    float4 gb = g4[lane + 32],   sb = s4[lane + 32];
    float a = ga.x * sa.x + ga.y * sa.y + ga.z * sa.z + ga.w * sa.w
            + gb.x * sb.x + gb.y * sb.y + gb.z * sb.z + gb.w * sb.w;
    return warp_sum(a);
}

// ---------------- kernel 1: init node->batch map -------------------------
__global__ void init_map_kernel(int nv) {
    int i = blockIdx.x * blockDim.x + threadIdx.x;
    int lim = nv < MAP_CAP ? nv : MAP_CAP;
    if (i < lim) g_map[i] = -1;
}

// ---------------- kernel 2: probe dtype + reset counter + scatter map ----
// single block, 256 threads. Runs after init_map on the same stream.
__global__ void setup_kernel(const int* src32, int ne,
                             const void* glob_idx, int b) {
    __shared__ int ok[8];
    __shared__ int sh_is64;
    int t = threadIdx.x;
    int n = ne < 256 ? ne : 256;
    // int64 (nonneg, < 2^31): every odd 32-bit word is 0.
    int odd_zero = (t < n) ? (src32[2 * t + 1] == 0) : 1;
    unsigned m = __ballot_sync(0xffffffffu, odd_zero);
    if ((t & 31) == 0) ok[t >> 5] = (m == 0xffffffffu);
    __syncthreads();
    if (t == 0) {
        int a = 1;
#pragma unroll
        for (int i = 0; i < 8; i++) a &= ok[i];
        sh_is64 = a;
        g_is64 = a;
        g_count = 0;
    }
    __syncthreads();
    int is64 = sh_is64;
    for (int i = t; i < b; i += blockDim.x) {
        long long node = idx_at(glob_idx, i, is64);
        if (node >= 0 && node < MAP_CAP) g_map[node] = i;
    }
}

// ---------------- kernel 3: qb[b][o] = sum_k query[b][k] * WQ[o][k] ------
// one block per batch row, 8 warps, warp-per-output (coalesced float4 reads)
__global__ void qb_kernel(const float* __restrict__ query,
                          const float* __restrict__ WQ) {
    __shared__ __align__(16) float qrow[D];
    int b = blockIdx.x, t = threadIdx.x;
    int warp = t >> 5, lane = t & 31;

    qrow[t] = query[(size_t)b * D + t];
    __syncthreads();

#pragma unroll
    for (int j = 0; j < 32; j++) {
        int o = warp * 32 + j;
        float a = warp_dot256(WQ + (size_t)o * D, qrow, lane);
        if (lane == 0) g_qb[(size_t)b * D + o] = a;
    }
}

// ---------------- kernel 4: qwk[b][h][c] = 0.125 * sum_d qb[b][h*64+d]*WK[h*64+d][c]
// grid = B*H blocks, 256 threads; WK reads coalesced in c=t
__global__ void qwk2_kernel(const float* __restrict__ WK) {
    __shared__ float qseg[DK];
    int blk = blockIdx.x;
    int b = blk >> 2, h = blk & 3;
    int t = threadIdx.x;

    if (t < DK) qseg[t] = g_qb[(size_t)b * D + h * DK + t];
    __syncthreads();

    float a = 0.f;
#pragma unroll 8
    for (int d = 0; d < DK; d++)
        a += qseg[d] * WK[(size_t)(h * DK + d) * D + t];
    g_qwk[((size_t)b * H + h) * D + t] = a * 0.125f;  // 1/sqrt(64)
}

// ---------------- kernel 5: filter + compact relevant edges --------------
__global__ void filter_kernel(const void* __restrict__ src,
                              const void* __restrict__ dst, int ne) {
    int is64 = g_is64;
    int stride = gridDim.x * blockDim.x;
    for (int i = blockIdx.x * blockDim.x + threadIdx.x; i < ne; i += stride) {
        long long d = idx_at(dst, i, is64);
        if (d >= 0 && d < MAP_CAP) {
            int b = g_map[d];
            if (b >= 0) {
                int pos = atomicAdd(&g_count, 1);
                if (pos < COMP_CAP) {
                    g_csrc[pos] = (int)idx_at(src, i, is64);
                    g_cb[pos]   = b;
                    g_ce[pos]   = i;
                }
            }
        }
    }
}

// ---------------- kernel 6: per-batch-row attention + WV + WO ------------
// one block per batch row b, 256 threads
__global__ void attn_kernel(const float* __restrict__ x,
                            const float* __restrict__ WV,
                            const float* __restrict__ WO,
                            float* __restrict__ out) {
    int b = blockIdx.x, t = threadIdx.x;
    int warp = t >> 5, lane = t & 31;

    __shared__ int   s_src[MAXE];
    __shared__ int   s_eid[MAXE];
    __shared__ float s_s[MAXE][H];                    // scores -> alphas
    __shared__ __align__(16) float s_buf[H][D];       // qwk, later xacc
    __shared__ __align__(16) float s_row[D];
    __shared__ int   s_cnt, s_me;

    if (t == 0) s_cnt = 0;
#pragma unroll
    for (int h = 0; h < H; h++)
        s_buf[h][t] = g_qwk[((size_t)b * H + h) * D + t];
    __syncthreads();

    // gather this row's edges (parallel, then sort by edge id => deterministic)
    int cnt = g_count;
    if (cnt > COMP_CAP) cnt = COMP_CAP;
    for (int p = t; p < cnt; p += blockDim.x) {
        if (g_cb[p] == b) {
            int q = atomicAdd(&s_cnt, 1);
            if (q < MAXE) { s_src[q] = g_csrc[p]; s_eid[q] = g_ce[p]; }
        }
    }
    __syncthreads();
    if (t == 0) {
        int me = s_cnt < MAXE ? s_cnt : MAXE;
        for (int i = 1; i < me; i++) {   // insertion sort by original edge id
            int e = s_eid[i], sv = s_src[i];
            int j = i - 1;
            while (j >= 0 && s_eid[j] > e) {
                s_eid[j + 1] = s_eid[j]; s_src[j + 1] = s_src[j]; j--;
            }
            s_eid[j + 1] = e; s_src[j + 1] = sv;
        }
        s_me = me;
    }
    __syncthreads();
    int me = s_me;

    // scores: warp per (edge, head) pair; x rows read as float4 (rows 1KB-aligned)
    for (int p = warp; p < me * H; p += 8) {
        int i = p >> 2, h = p & 3;
        float a = warp_dot256(x + (size_t)s_src[i] * D, s_buf[h], lane);
        if (lane == 0) s_s[i][h] = a;
    }
    __syncthreads();

    // softmax per head (tiny, serial per head)
    if (t < H) {
        float m = -1e30f;
        for (int i = 0; i < me; i++) m = fmaxf(m, s_s[i][t]);
        float sum = 0.f;
        for (int i = 0; i < me; i++) {
            float e = __expf(s_s[i][t] - m);
            s_s[i][t] = e; sum += e;
        }
        float inv = sum > 0.f ? 1.f / sum : 0.f;
        for (int i = 0; i < me; i++) s_s[i][t] *= inv;
    }
    __syncthreads();

    // aggregate: xacc[h][c] = sum_i alpha[i][h] * x[src_i][c]  (c = t, coalesced)
    float a0 = 0.f, a1 = 0.f, a2 = 0.f, a3 = 0.f;
    for (int i = 0; i < me; i++) {
        float xv = x[(size_t)s_src[i] * D + t];
        a0 += s_s[i][0] * xv; a1 += s_s[i][1] * xv;
        a2 += s_s[i][2] * xv; a3 += s_s[i][3] * xv;
    }
    __syncthreads();               // done reading s_buf as qwk
    s_buf[0][t] = a0; s_buf[1][t] = a1; s_buf[2][t] = a2; s_buf[3][t] = a3;
    __syncthreads();

    // V projection: row[o] = sum_c xacc[h(o)][c] * WV[o][c]  -- warp per output
#pragma unroll
    for (int j = 0; j < 32; j++) {
        int o = warp * 32 + j;
        int h = o >> 6;
        float a = warp_dot256(WV + (size_t)o * D, s_buf[h], lane);
        if (lane == 0) s_row[o] = a;
    }
    __syncthreads();

    // O projection: out[b][o] = sum_k row[k] * WO[o][k]  -- warp per output
#pragma unroll
    for (int j = 0; j < 32; j++) {
        int o = warp * 32 + j;
        float a = warp_dot256(WO + (size_t)o * D, s_row, lane);
        if (lane == 0) out[(size_t)b * D + o] = a;
    }
}

// ---------------- launch ------------------------------------------------
extern "C" void kernel_launch(void* const* d_in, const int* in_sizes, int n_in,
                              void* d_out, int out_size) {
    const float* query = (const float*)d_in[0];
    const float* x     = (const float*)d_in[1];
    const float* WQ    = (const float*)d_in[2];
    const float* WK    = (const float*)d_in[3];
    const float* WV    = (const float*)d_in[4];
    const float* WO    = (const float*)d_in[5];
    const void*  src   = d_in[6];
    const void*  dst   = d_in[7];
    const void*  gidx  = d_in[8];

    int B  = in_sizes[0] / D;
    int NV = in_sizes[1] / D;
    int NE = in_sizes[6];
    float* out = (float*)d_out;

    init_map_kernel<<<(NV + 255) / 256, 256>>>(NV);
    setup_kernel<<<1, 256>>>((const int*)src, NE, gidx, B);
    qb_kernel<<<B, 256>>>(query, WQ);
    qwk2_kernel<<<B * H, 256>>>(WK);
    filter_kernel<<<(NE + 255) / 256, 256>>>(src, dst, NE);
    attn_kernel<<<B, 256>>>(x, WV, WO, out);
}

// round 11
// speedup vs baseline: 3.8042x; 1.1146x over previous
#include <cuda_runtime.h>

#define D   256
#define H   4
#define DK  64

#define COMP_CAP  16384
#define MAXE      256
#define BMAX      256
#define HASH      512

// ---------------- device scratch (no allocations allowed) ----------------
__device__ int   g_count;
__device__ int   g_csrc[COMP_CAP];
__device__ int   g_cb[COMP_CAP];
__device__ int   g_ce[COMP_CAP];
__device__ float g_qwk[BMAX * H * D];

__device__ __forceinline__ long long idx_at(const void* p, long long i, int is64) {
    if (is64) return ((const long long*)p)[i];
    return (long long)((const int*)p)[i];
}

__device__ __forceinline__ float warp_sum(float a) {
#pragma unroll
    for (int o = 16; o; o >>= 1) a += __shfl_down_sync(0xffffffffu, a, o);
    return a;
}

// dot of a 256-float global row with a 256-float shared row, one warp, float4.
__device__ __forceinline__ float warp_dot256(const float* __restrict__ g,
                                             const float* __restrict__ s,
                                             int lane) {
    const float4* g4 = (const float4*)g;
    const float4* s4 = (const float4*)s;
    float4 ga = g4[lane],        sa = s4[lane];
    float4 gb = g4[lane + 32],   sb = s4[lane + 32];
    float a = ga.x * sa.x + ga.y * sa.y + ga.z * sa.z + ga.w * sa.w
            + gb.x * sb.x + gb.y * sb.y + gb.z * sb.z + gb.w * sb.w;
    return warp_sum(a);
}

// ---------------- kernel 1: fused qb + qwk -------------------------------
// grid = B*H blocks (b = blk>>2, h = blk&3), 256 threads.
// phase 1: qseg[j] = query[b] . WQ[h*64+j]    (8 warps x 8 warp-dots)
// phase 2: qwk[b][h][c] = 0.125 * sum_d qseg[d] * WK[h*64+d][c]
//          float4 column tiling: thread (ty,tx) covers cols 4tx..4tx+3,
//          d in {ty, ty+4, ...} -> 16 independent LDG.128 per thread.
__global__ void fused_q_kernel(const float* __restrict__ query,
                               const float* __restrict__ WQ,
                               const float* __restrict__ WK) {
    __shared__ __align__(16) float qrow[D];
    __shared__ float qseg[DK];
    __shared__ __align__(16) float4 red[4][64];

    int blk = blockIdx.x;
    int b = blk >> 2, h = blk & 3;
    int t = threadIdx.x;
    int warp = t >> 5, lane = t & 31;

    if (blk == 0 && t == 0) g_count = 0;   // stream-ordered reset for filter

    qrow[t] = query[(size_t)b * D + t];
    __syncthreads();

    // phase 1
#pragma unroll
    for (int j = 0; j < 8; j++) {
        int ol = warp * 8 + j;                       // 0..63
        float a = warp_dot256(WQ + (size_t)(h * DK + ol) * D, qrow, lane);
        if (lane == 0) qseg[ol] = a;
    }
    __syncthreads();

    // phase 2
    int ty = t >> 6, tx = t & 63;
    float4 acc = make_float4(0.f, 0.f, 0.f, 0.f);
#pragma unroll
    for (int i = 0; i < 16; i++) {
        int d = ty + i * 4;
        float qd = qseg[d];
        float4 w = ((const float4*)(WK + (size_t)(h * DK + d) * D))[tx];
        acc.x += qd * w.x; acc.y += qd * w.y;
        acc.z += qd * w.z; acc.w += qd * w.w;
    }
    red[ty][tx] = acc;
    __syncthreads();
    if (ty == 0) {
        float4 r0 = red[0][tx], r1 = red[1][tx], r2 = red[2][tx], r3 = red[3][tx];
        float4 r;
        r.x = (r0.x + r1.x + r2.x + r3.x) * 0.125f;
        r.y = (r0.y + r1.y + r2.y + r3.y) * 0.125f;
        r.z = (r0.z + r1.z + r2.z + r3.z) * 0.125f;
        r.w = (r0.w + r1.w + r2.w + r3.w) * 0.125f;
        ((float4*)(g_qwk + ((size_t)b * H + h) * D))[tx] = r;
    }
}

// ---------------- kernel 2: filter via per-block shared hash -------------
__global__ void filter_kernel(const void* __restrict__ src,
                              const void* __restrict__ dst, int ne,
                              const void* __restrict__ glob_idx, int b) {
    __shared__ int hkey[HASH];
    __shared__ int hval[HASH];
    __shared__ int ok[8];
    __shared__ int sh_is64;

    int t = threadIdx.x;

    // dtype probe: int64 (nonneg < 2^31) => odd 32-bit words all zero
    int n = ne < 256 ? ne : 256;
    int odd_zero = (t < n) ? (((const int*)src)[2 * t + 1] == 0) : 1;
    unsigned m = __ballot_sync(0xffffffffu, odd_zero);
    if ((t & 31) == 0) ok[t >> 5] = (m == 0xffffffffu);

    for (int i = t; i < HASH; i += 256) { hkey[i] = -1; hval[i] = -1; }
    __syncthreads();
    if (t == 0) {
        int a = 1;
#pragma unroll
        for (int i = 0; i < 8; i++) a &= ok[i];
        sh_is64 = a;
    }
    __syncthreads();
    int is64 = sh_is64;

    // build hash from glob_idx (atomicMax on val => deterministic on dups)
    for (int i = t; i < b; i += 256) {
        int node = (int)idx_at(glob_idx, i, is64);
        int s = node & (HASH - 1);
        for (;;) {
            int prev = atomicCAS(&hkey[s], -1, node);
            if (prev == -1 || prev == node) { atomicMax(&hval[s], i); break; }
            s = (s + 1) & (HASH - 1);
        }
    }
    __syncthreads();

    // edges
    int stride = gridDim.x * blockDim.x;
    for (int i = blockIdx.x * blockDim.x + t; i < ne; i += stride) {
        int dv = (int)idx_at(dst, i, is64);
        int s = dv & (HASH - 1);
        int bf = -1;
        for (;;) {
            int k = hkey[s];
            if (k == -1) break;
            if (k == dv) { bf = hval[s]; break; }
            s = (s + 1) & (HASH - 1);
        }
        if (bf >= 0) {
            int pos = atomicAdd(&g_count, 1);
            if (pos < COMP_CAP) {
                g_csrc[pos] = (int)idx_at(src, i, is64);
                g_cb[pos]   = bf;
                g_ce[pos]   = i;
            }
        }
    }
}

// ---------------- kernel 3: per-batch-row attention + WV + WO ------------
// one block per batch row b, 512 threads (16 warps)
__global__ void attn_kernel(const float* __restrict__ x,
                            const float* __restrict__ WV,
                            const float* __restrict__ WO,
                            float* __restrict__ out) {
    int b = blockIdx.x, t = threadIdx.x;
    int warp = t >> 5, lane = t & 31;

    __shared__ int   s_src[MAXE];
    __shared__ int   s_eid[MAXE];
    __shared__ float s_s[MAXE][H];                 // scores -> alphas
    __shared__ __align__(16) float s_buf[H][D];    // qwk, later xacc
    __shared__ __align__(16) float s_row[D];
    __shared__ int   s_cnt, s_me;

    if (t == 0) s_cnt = 0;
    if (t < D) {
#pragma unroll
        for (int h = 0; h < H; h++)
            s_buf[h][t] = g_qwk[((size_t)b * H + h) * D + t];
    }
    __syncthreads();

    // gather this row's edges, then sort by edge id => deterministic
    int cnt = g_count;
    if (cnt > COMP_CAP) cnt = COMP_CAP;
    for (int p = t; p < cnt; p += blockDim.x) {
        if (g_cb[p] == b) {
            int q = atomicAdd(&s_cnt, 1);
            if (q < MAXE) { s_src[q] = g_csrc[p]; s_eid[q] = g_ce[p]; }
        }
    }
    __syncthreads();
    if (t == 0) {
        int me = s_cnt < MAXE ? s_cnt : MAXE;
        for (int i = 1; i < me; i++) {
            int e = s_eid[i], sv = s_src[i];
            int j = i - 1;
            while (j >= 0 && s_eid[j] > e) {
                s_eid[j + 1] = s_eid[j]; s_src[j + 1] = s_src[j]; j--;
            }
            s_eid[j + 1] = e; s_src[j + 1] = sv;
        }
        s_me = me;
    }
    __syncthreads();
    int me = s_me;

    // scores: warp per (edge, head); x rows float4-coalesced; 16 warps
    for (int p = warp; p < me * H; p += 16) {
        int i = p >> 2, h = p & 3;
        float a = warp_dot256(x + (size_t)s_src[i] * D, s_buf[h], lane);
        if (lane == 0) s_s[i][h] = a;
    }
    __syncthreads();

    // softmax per head
    if (t < H) {
        float mx = -1e30f;
        for (int i = 0; i < me; i++) mx = fmaxf(mx, s_s[i][t]);
        float sum = 0.f;
        for (int i = 0; i < me; i++) {
            float e = __expf(s_s[i][t] - mx);
            s_s[i][t] = e; sum += e;
        }
        float inv = sum > 0.f ? 1.f / sum : 0.f;
        for (int i = 0; i < me; i++) s_s[i][t] *= inv;
    }
    __syncthreads();

    // aggregate: xacc[h][c] = sum_i alpha[i][h] * x[src_i][c]  (c = t < 256)
    float a0 = 0.f, a1 = 0.f, a2 = 0.f, a3 = 0.f;
    if (t < D) {
        for (int i = 0; i < me; i++) {
            float xv = x[(size_t)s_src[i] * D + t];
            a0 += s_s[i][0] * xv; a1 += s_s[i][1] * xv;
            a2 += s_s[i][2] * xv; a3 += s_s[i][3] * xv;
        }
    }
    __syncthreads();               // done reading s_buf as qwk
    if (t < D) {
        s_buf[0][t] = a0; s_buf[1][t] = a1; s_buf[2][t] = a2; s_buf[3][t] = a3;
    }
    __syncthreads();

    // V projection: 16 warps x 16 outputs
#pragma unroll
    for (int j = 0; j < 16; j++) {
        int o = warp * 16 + j;
        int h = o >> 6;
        float a = warp_dot256(WV + (size_t)o * D, s_buf[h], lane);
        if (lane == 0) s_row[o] = a;
    }
    __syncthreads();

    // O projection: 16 warps x 16 outputs
#pragma unroll
    for (int j = 0; j < 16; j++) {
        int o = warp * 16 + j;
        float a = warp_dot256(WO + (size_t)o * D, s_row, lane);
        if (lane == 0) out[(size_t)b * D + o] = a;
    }
}

// ---------------- launch ------------------------------------------------
extern "C" void kernel_launch(void* const* d_in, const int* in_sizes, int n_in,
                              void* d_out, int out_size) {
    const float* query = (const float*)d_in[0];
    const float* x     = (const float*)d_in[1];
    const float* WQ    = (const float*)d_in[2];
    const float* WK    = (const float*)d_in[3];
    const float* WV    = (const float*)d_in[4];
    const float* WO    = (const float*)d_in[5];
    const void*  src   = d_in[6];
    const void*  dst   = d_in[7];
    const void*  gidx  = d_in[8];

    int B  = in_sizes[0] / D;
    int NE = in_sizes[6];
    float* out = (float*)d_out;

    fused_q_kernel<<<B * H, 256>>>(query, WQ, WK);
    int fblocks = (NE + 255) / 256;
    if (fblocks > 592) fblocks = 592;          // <= 4 waves, grid-stride covers rest
    filter_kernel<<<fblocks, 256>>>(src, dst, NE, gidx, B);
    attn_kernel<<<B, 512>>>(x, WV, WO, out);
}